// round 4
// baseline (speedup 1.0000x reference)
#include <cuda_runtime.h>
#include <cstdint>

// ---------------- problem constants ----------------
#define BB     8
#define NN     8192
#define CIN    32
#define COUT   32
#define NS     2
#define JCOLS  256        // B * C_OUT

// ---------------- GEMM tiling ----------------
#define BM     128
#define BN     256        // full J width -> supports read exactly once
#define BK     32         // 32 f32 = 128 B per row
#define PADW   36         // padded row stride in words (144 B, 16B-aligned, conflict-free frags)
#define ASTGW  (BM * PADW)            // 4608 words
#define BSTGW  (BN * PADW)            // 9216 words
#define STGW   (ASTGW + BSTGW)        // 13824 words = 55296 B / stage
#define NSTAGE 4
#define SMEM_BYTES (NSTAGE * STGW * 4)  // 221184 B
#define NKT    (NN / BK)              // 256 k-iterations

// ---------------- scratch (no allocation allowed) ----------------
__device__ __align__(1024) float g_yt[(size_t)NS * JCOLS * NN];    // [s][j][m]
__device__ __align__(1024) float g_part[(size_t)NS * NN * JCOLS];  // [s][n][j]

// ---------------- PTX helpers (sm_80-base features ONLY) ----------------
static __device__ __forceinline__ uint32_t smem_u32(const void* p) {
    uint32_t a;
    asm("{ .reg .u64 t; cvta.to.shared.u64 t, %1; cvt.u32.u64 %0, t; }" : "=r"(a) : "l"(p));
    return a;
}

#define CP16(dst, src) \
    asm volatile("cp.async.cg.shared.global [%0], [%1], 16;" :: "r"(dst), "l"(src) : "memory")
#define CPCOMMIT() asm volatile("cp.async.commit_group;" ::: "memory")
#define CPWAIT(n)  asm volatile("cp.async.wait_group %0;" :: "n"(n) : "memory")

// m16n8k8 tf32 MMA; HW truncates f32 operands to tf32.
#define MMA_TF32(d, a, b) \
    asm volatile("mma.sync.aligned.m16n8k8.row.col.f32.tf32.tf32.f32 " \
                 "{%0,%1,%2,%3}, {%4,%5,%6,%7}, {%8,%9}, {%0,%1,%2,%3};" \
                 : "+f"((d)[0]), "+f"((d)[1]), "+f"((d)[2]), "+f"((d)[3]) \
                 : "r"((a)[0]), "r"((a)[1]), "r"((a)[2]), "r"((a)[3]), \
                   "r"((b)[0]), "r"((b)[1]))

// ---- kernel 1: Yt[s][j][m] = sum_c x[b][m][c] * W[s][o][c], j = b*32+o ----
// Output pre-rounded to tf32-RN so the GEMM's B operand carries no truncation bias.
__global__ void __launch_bounds__(256) yt_kernel(const float* __restrict__ x,
                                                 const float* __restrict__ W) {
    __shared__ float xs[BB * 32 * CIN];  // 32 KB
    __shared__ float ws[COUT * 33];
    int s  = blockIdx.y;
    int m0 = blockIdx.x * 32;
    int t  = threadIdx.x;

    for (int i = t; i < COUT * CIN; i += 256)
        ws[(i >> 5) * 33 + (i & 31)] = W[s * COUT * CIN + i];
    for (int i = t; i < BB * 32 * CIN; i += 256) {
        int b = i >> 10;
        int r = i & 1023;
        xs[i] = x[(size_t)b * NN * CIN + (size_t)m0 * CIN + r];
    }
    __syncthreads();

    int b = t >> 5, o = t & 31;
    const float* xr = xs + b * 1024;
    const float* wr = ws + o * 33;
    float* dst = g_yt + ((size_t)s * JCOLS + t) * NN + m0;   // j == t
    for (int ml = 0; ml < 32; ++ml) {
        float acc = 0.f;
#pragma unroll
        for (int c = 0; c < CIN; ++c)
            acc = fmaf(xr[ml * 32 + c], wr[c], acc);
        uint32_t u;
        asm("cvt.rna.tf32.f32 %0, %1;" : "=r"(u) : "f"(acc));
        dst[ml] = __uint_as_float(u);
    }
}

// ---- kernel 2: tf32 mma.sync GEMM: part[s][n][j] = supports[s][n][:].Yt[s][j][:] ----
// Grid (64, 2): 128 CTAs = one wave. CTA 128x256, 8 warps of 64x64, 4-stage cp.async.
__global__ void __launch_bounds__(256, 1) gemm_kernel(const float* __restrict__ supports) {
    extern __shared__ float sm[];
    int tid  = threadIdx.x;
    int lane = tid & 31, w = tid >> 5;
    int g = lane >> 2, t = lane & 3;          // mma quad coords
    int wm = w >> 2, wn = w & 3;              // warp grid 2 (M) x 4 (N)
    int n0 = blockIdx.x * BM;
    int s  = blockIdx.y;

    const float* Abase = supports + ((size_t)s * NN + n0) * NN;
    const float* Bbase = g_yt + (size_t)s * JCOLS * NN;

    // 12 cp.async 16B chunks per thread per stage (A: 1024 chunks, B: 2048)
    const float* gsrc[12];
    int sdst[12];
#pragma unroll
    for (int i = 0; i < 12; ++i) {
        int idx = i * 256 + tid;
        if (idx < 1024) {
            int r = idx >> 3, c = idx & 7;
            sdst[i] = r * PADW + c * 4;
            gsrc[i] = Abase + (size_t)r * NN + c * 4;
        } else {
            int bi = idx - 1024;
            int r = bi >> 3, c = bi & 7;
            sdst[i] = ASTGW + r * PADW + c * 4;
            gsrc[i] = Bbase + (size_t)r * NN + c * 4;
        }
    }
    uint32_t smbase = smem_u32(sm);

    // prologue: fill 3 stages
#pragma unroll
    for (int p = 0; p < NSTAGE - 1; ++p) {
        uint32_t sb = smbase + p * (STGW * 4);
#pragma unroll
        for (int i = 0; i < 12; ++i)
            CP16(sb + sdst[i] * 4, gsrc[i] + p * BK);
        CPCOMMIT();
    }

    float acc[4][8][4];
#pragma unroll
    for (int mt = 0; mt < 4; ++mt)
#pragma unroll
        for (int nt = 0; nt < 8; ++nt)
#pragma unroll
            for (int r = 0; r < 4; ++r) acc[mt][nt][r] = 0.f;

    for (int kt = 0; kt < NKT; ++kt) {
        CPWAIT(2);            // oldest group (stage kt) complete for THIS thread
        __syncthreads();      // ... and for all threads; also guards slot reuse
        int kn = kt + NSTAGE - 1;
        if (kn < NKT) {       // refill slot (kn & 3) == slot of consumed stage kt-1
            uint32_t sb = smbase + (kn & 3) * (STGW * 4);
#pragma unroll
            for (int i = 0; i < 12; ++i)
                CP16(sb + sdst[i] * 4, gsrc[i] + (size_t)kn * BK);
            CPCOMMIT();
        }
        const uint32_t* As = (const uint32_t*)sm + (kt & 3) * STGW;
        const uint32_t* Bs = As + ASTGW;
#pragma unroll
        for (int kk = 0; kk < 4; ++kk) {
            int kb = kk * 8;
            uint32_t af[4][4], bf[8][2];
#pragma unroll
            for (int mt = 0; mt < 4; ++mt) {
                const uint32_t* ap = As + (wm * 64 + mt * 16 + g) * PADW + kb + t;
                af[mt][0] = ap[0];                 // (g,      k=t)
                af[mt][1] = ap[8 * PADW];          // (g+8,    k=t)
                af[mt][2] = ap[4];                 // (g,      k=t+4)
                af[mt][3] = ap[8 * PADW + 4];      // (g+8,    k=t+4)
            }
#pragma unroll
            for (int nt = 0; nt < 8; ++nt) {
                const uint32_t* bp = Bs + (wn * 64 + nt * 8 + g) * PADW + kb + t;
                bf[nt][0] = bp[0];                 // (k=t,   n=g)
                bf[nt][1] = bp[4];                 // (k=t+4, n=g)
            }
#pragma unroll
            for (int mt = 0; mt < 4; ++mt)
#pragma unroll
                for (int nt = 0; nt < 8; ++nt)
                    MMA_TF32(acc[mt][nt], af[mt], bf[nt]);
        }
    }

    // epilogue: c0,c1 = (row, 2t..2t+1); c2,c3 = (row+8, 2t..2t+1)
    float* dst = g_part + ((size_t)s * NN + n0) * JCOLS;
#pragma unroll
    for (int mt = 0; mt < 4; ++mt) {
#pragma unroll
        for (int nt = 0; nt < 8; ++nt) {
            int row = wm * 64 + mt * 16 + g;
            int col = wn * 64 + nt * 8 + 2 * t;
            float2 v0 = make_float2(acc[mt][nt][0], acc[mt][nt][1]);
            float2 v1 = make_float2(acc[mt][nt][2], acc[mt][nt][3]);
            *(float2*)(dst + (size_t)row * JCOLS + col)       = v0;
            *(float2*)(dst + (size_t)(row + 8) * JCOLS + col) = v1;
        }
    }
}

// ---- kernel 3: out[b][n][o] = (part0 + part1) * corr + bias[o] ----
__global__ void __launch_bounds__(256) reduce_kernel(const float* __restrict__ bias,
                                                     float* __restrict__ out) {
    int idx = blockIdx.x * 256 + threadIdx.x;  // 8*8192*32 = 2^21
    int o = idx & 31;
    int n = (idx >> 5) & (NN - 1);
    int b = idx >> 18;
    int p = n * JCOLS + (b << 5) + o;
    const float corr = 1.000244f;  // compensate tf32 truncation of the A operand
    out[idx] = (g_part[p] + g_part[(size_t)NN * JCOLS + p]) * corr + bias[o];
}

// ---------------- host ----------------
extern "C" void kernel_launch(void* const* d_in, const int* in_sizes, int n_in,
                              void* d_out, int out_size) {
    const float* x        = (const float*)d_in[0];
    const float* supports = (const float*)d_in[1];
    const float* W        = (const float*)d_in[2];
    const float* bias     = (const float*)d_in[3];
    float* out            = (float*)d_out;
    (void)in_sizes; (void)n_in; (void)out_size;

    cudaFuncSetAttribute(gemm_kernel, cudaFuncAttributeMaxDynamicSharedMemorySize, SMEM_BYTES);

    yt_kernel<<<dim3(NN / 32, NS), 256>>>(x, W);
    gemm_kernel<<<dim3(NN / BM, NS), 256, SMEM_BYTES>>>(supports);
    reduce_kernel<<<(BB * NN * COUT) / 256, 256>>>(bias, out);
}

// round 8
// speedup vs baseline: 1.0606x; 1.0606x over previous
#include <cuda_runtime.h>
#include <cstdint>

// ---------------- problem constants ----------------
#define BB     8
#define NN     8192
#define CIN    32
#define COUT   32
#define NS     2
#define JCOLS  256        // B * C_OUT

// ---------------- GEMM tiling ----------------
#define BM     128
#define BN     256        // full J width -> supports read exactly once
#define BK     32         // 32 f32 = 128 B per row
#define PADW   36         // padded row stride (words); rows offset 4 banks -> LDSM conflict-free
#define ASTGW  (BM * PADW)            // 4608 words
#define BSTGW  (BN * PADW)            // 9216 words
#define STGW   (ASTGW + BSTGW)        // 13824 words / stage
#define NSTAGE 4
#define SMEM_BYTES (NSTAGE * STGW * 4)  // 221184 B
#define NKT    (NN / BK)              // 256

// ---------------- scratch ----------------
__device__ __align__(1024) float g_yt[(size_t)NS * JCOLS * NN];    // [s][j][m]
__device__ __align__(1024) float g_part[(size_t)NS * NN * JCOLS];  // [s][n][j]

// ---------------- PTX helpers (<= sm_80 base features only) ----------------
static __device__ __forceinline__ uint32_t smem_u32(const void* p) {
    uint32_t a;
    asm("{ .reg .u64 t; cvta.to.shared.u64 t, %1; cvt.u32.u64 %0, t; }" : "=r"(a) : "l"(p));
    return a;
}
#define CP16(dst, src) \
    asm volatile("cp.async.cg.shared.global [%0], [%1], 16;" :: "r"(dst), "l"(src) : "memory")
#define CPCOMMIT() asm volatile("cp.async.commit_group;" ::: "memory")
#define CPWAIT(n)  asm volatile("cp.async.wait_group %0;" :: "n"(n) : "memory")

#define LDSM_X4(r0, r1, r2, r3, addr) \
    asm volatile("ldmatrix.sync.aligned.m8n8.x4.shared.b16 {%0,%1,%2,%3}, [%4];" \
                 : "=r"(r0), "=r"(r1), "=r"(r2), "=r"(r3) : "r"(addr))

#define MMA_TF32(d, a, b) \
    asm volatile("mma.sync.aligned.m16n8k8.row.col.f32.tf32.tf32.f32 " \
                 "{%0,%1,%2,%3}, {%4,%5,%6,%7}, {%8,%9}, {%0,%1,%2,%3};" \
                 : "+f"((d)[0]), "+f"((d)[1]), "+f"((d)[2]), "+f"((d)[3]) \
                 : "r"((a)[0]), "r"((a)[1]), "r"((a)[2]), "r"((a)[3]), \
                   "r"((b)[0]), "r"((b)[1]))

// ---- kernel 1: Yt[s][j][m] = sum_c x[b][m][c] * W[s][o][c], j = b*32+o ----
// smem layout: xs[8][32][32] | ws[32][33] | outs[256][33]; fully coalesced I/O.
#define YT_XS_W   (BB * 32 * CIN)        // 8192
#define YT_WS_W   (COUT * 33)            // 1056
#define YT_OUT_W  (JCOLS * 33)           // 8448
#define YT_SMEM   ((YT_XS_W + YT_WS_W + YT_OUT_W) * 4)  // 70784 B

__global__ void __launch_bounds__(256) yt_kernel(const float* __restrict__ x,
                                                 const float* __restrict__ W) {
    extern __shared__ float sm[];
    float* xs   = sm;                 // [b][m][c]
    float* ws   = sm + YT_XS_W;       // [o][33]
    float* outs = ws + YT_WS_W;       // [j][33]
    int s  = blockIdx.y;
    int m0 = blockIdx.x * 32;
    int t  = threadIdx.x;

    for (int i = t; i < COUT * CIN; i += 256)
        ws[(i >> 5) * 33 + (i & 31)] = W[s * COUT * CIN + i];
    for (int i = t; i < YT_XS_W; i += 256) {
        int b = i >> 10;                       // 32m*32c = 1024 per b
        xs[i] = x[(size_t)b * NN * CIN + (size_t)m0 * CIN + (i & 1023)];
    }
    __syncthreads();

    int b = t >> 5, o = t & 31;                // warp = b, lane = o
    float wr[32];
#pragma unroll
    for (int c = 0; c < 32; ++c) wr[c] = ws[o * 33 + c];   // stride-33: conflict-free

    const float4* xr = (const float4*)(xs + b * 1024);     // warp-broadcast reads
    float* orow = outs + t * 33;
    for (int m = 0; m < 32; ++m) {
        float acc = 0.f;
#pragma unroll
        for (int q = 0; q < 8; ++q) {
            float4 v = xr[m * 8 + q];
            acc = fmaf(v.x, wr[q * 4 + 0], acc);
            acc = fmaf(v.y, wr[q * 4 + 1], acc);
            acc = fmaf(v.z, wr[q * 4 + 2], acc);
            acc = fmaf(v.w, wr[q * 4 + 3], acc);
        }
        uint32_t u;                            // pre-round B operand to tf32-RN
        asm("cvt.rna.tf32.f32 %0, %1;" : "=r"(u) : "f"(acc));
        orow[m] = __uint_as_float(u);
    }
    __syncthreads();

    // coalesced store: warp writes one 32-float row segment per step
    for (int i = t; i < JCOLS * 32; i += 256) {
        int j = i >> 5, mm = i & 31;
        g_yt[((size_t)s * JCOLS + j) * NN + m0 + mm] = outs[j * 33 + mm];
    }
}

// ---- kernel 2: tf32 mma.sync GEMM via ldmatrix. 128 CTAs, 8 warps of 64x64 ----
__global__ void __launch_bounds__(256, 1) gemm_kernel(const float* __restrict__ supports) {
    extern __shared__ float sm[];
    int tid  = threadIdx.x;
    int lane = tid & 31, w = tid >> 5;
    int wm = w >> 2, wn = w & 3;              // warp grid 2 (M) x 4 (N)
    int n0 = blockIdx.x * BM;
    int s  = blockIdx.y;

    const float* Abase = supports + ((size_t)s * NN + n0) * NN;
    const float* Bbase = g_yt + (size_t)s * JCOLS * NN;
    uint32_t smbase = smem_u32(sm);

    // ldmatrix per-lane address components (words)
    // A frag (m16k8): tiles (rows0-7,k0-3)(rows8-15,k0-3)(rows0-7,k4-7)(rows8-15,k4-7)
    uint32_t a_lw = (uint32_t)((lane & 15) * PADW + ((lane >> 4) << 2));
    // B frag pair (two n8k8): tiles (n0-7,k0-3)(n0-7,k4-7)(n8-15,k0-3)(n8-15,k4-7)
    uint32_t b_lw = (uint32_t)((((lane >> 4) << 3) + (lane & 7)) * PADW + (((lane >> 3) & 1) << 2));

    // prologue: fill 3 stages
#pragma unroll
    for (int p = 0; p < NSTAGE - 1; ++p) {
        uint32_t sb = smbase + p * (STGW * 4);
#pragma unroll
        for (int i = 0; i < 12; ++i) {
            int idx = i * 256 + tid;
            int c = idx & 7;
            if (idx < 1024) {
                int r = idx >> 3;
                CP16(sb + (uint32_t)(r * PADW + c * 4) * 4,
                     Abase + (size_t)r * NN + c * 4 + (size_t)p * BK);
            } else {
                int r = (idx - 1024) >> 3;
                CP16(sb + (uint32_t)(ASTGW + r * PADW + c * 4) * 4,
                     Bbase + (size_t)r * NN + c * 4 + (size_t)p * BK);
            }
        }
        CPCOMMIT();
    }

    float acc[4][8][4];
#pragma unroll
    for (int mt = 0; mt < 4; ++mt)
#pragma unroll
        for (int nt = 0; nt < 8; ++nt)
#pragma unroll
            for (int r = 0; r < 4; ++r) acc[mt][nt][r] = 0.f;

    for (int kt = 0; kt < NKT; ++kt) {
        CPWAIT(2);
        __syncthreads();
        int kn = kt + NSTAGE - 1;
        if (kn < NKT) {                        // refill slot freed last iteration
            uint32_t sb = smbase + (kn & 3) * (STGW * 4);
#pragma unroll
            for (int i = 0; i < 12; ++i) {
                int idx = i * 256 + tid;
                int c = idx & 7;
                if (idx < 1024) {
                    int r = idx >> 3;
                    CP16(sb + (uint32_t)(r * PADW + c * 4) * 4,
                         Abase + (size_t)r * NN + c * 4 + (size_t)kn * BK);
                } else {
                    int r = (idx - 1024) >> 3;
                    CP16(sb + (uint32_t)(ASTGW + r * PADW + c * 4) * 4,
                         Bbase + (size_t)r * NN + c * 4 + (size_t)kn * BK);
                }
            }
            CPCOMMIT();
        }
        uint32_t As_u = smbase + (kt & 3) * (STGW * 4);
        uint32_t Bs_u = As_u + ASTGW * 4;
#pragma unroll
        for (int kk = 0; kk < 4; ++kk) {
            uint32_t af[4][4], bf[8][2];
#pragma unroll
            for (int mt = 0; mt < 4; ++mt) {
                uint32_t ad = As_u + ((uint32_t)((wm * 64 + mt * 16) * PADW + kk * 8) + a_lw) * 4;
                LDSM_X4(af[mt][0], af[mt][1], af[mt][2], af[mt][3], ad);
            }
#pragma unroll
            for (int np = 0; np < 4; ++np) {   // each LDSM.x4 feeds two nt
                uint32_t bd = Bs_u + ((uint32_t)((wn * 64 + np * 16) * PADW + kk * 8) + b_lw) * 4;
                LDSM_X4(bf[2 * np][0], bf[2 * np][1], bf[2 * np + 1][0], bf[2 * np + 1][1], bd);
            }
#pragma unroll
            for (int mt = 0; mt < 4; ++mt)
#pragma unroll
                for (int nt = 0; nt < 8; ++nt)
                    MMA_TF32(acc[mt][nt], af[mt], bf[nt]);
        }
    }

    // epilogue
    int g = lane >> 2, t4 = lane & 3;
    float* dst = g_part + ((size_t)s * NN + n0) * JCOLS;
#pragma unroll
    for (int mt = 0; mt < 4; ++mt) {
#pragma unroll
        for (int nt = 0; nt < 8; ++nt) {
            int row = wm * 64 + mt * 16 + g;
            int col = wn * 64 + nt * 8 + 2 * t4;
            *(float2*)(dst + (size_t)row * JCOLS + col) =
                make_float2(acc[mt][nt][0], acc[mt][nt][1]);
            *(float2*)(dst + (size_t)(row + 8) * JCOLS + col) =
                make_float2(acc[mt][nt][2], acc[mt][nt][3]);
        }
    }
}

// ---- kernel 3: out = (part0 + part1) * corr + bias, float4 ----
__global__ void __launch_bounds__(256) reduce_kernel(const float* __restrict__ bias,
                                                     float* __restrict__ out) {
    int idx = blockIdx.x * 256 + threadIdx.x;     // 2^19 threads, 4 elems each
    int o4 = (idx & 7) << 2;
    int n  = (idx >> 3) & (NN - 1);
    int b  = idx >> 16;
    size_t p = (size_t)n * JCOLS + (b << 5) + o4;
    const float4 p0 = *(const float4*)(g_part + p);
    const float4 p1 = *(const float4*)(g_part + (size_t)NN * JCOLS + p);
    const float4 bs = *(const float4*)(bias + o4);
    const float corr = 1.000244f;                 // tf32 truncation compensation (A side)
    float4 r;
    r.x = (p0.x + p1.x) * corr + bs.x;
    r.y = (p0.y + p1.y) * corr + bs.y;
    r.z = (p0.z + p1.z) * corr + bs.z;
    r.w = (p0.w + p1.w) * corr + bs.w;
    *(float4*)(out + 4 * (size_t)idx) = r;
}

// ---------------- host ----------------
extern "C" void kernel_launch(void* const* d_in, const int* in_sizes, int n_in,
                              void* d_out, int out_size) {
    const float* x        = (const float*)d_in[0];
    const float* supports = (const float*)d_in[1];
    const float* W        = (const float*)d_in[2];
    const float* bias     = (const float*)d_in[3];
    float* out            = (float*)d_out;
    (void)in_sizes; (void)n_in; (void)out_size;

    cudaFuncSetAttribute(gemm_kernel, cudaFuncAttributeMaxDynamicSharedMemorySize, SMEM_BYTES);
    cudaFuncSetAttribute(yt_kernel, cudaFuncAttributeMaxDynamicSharedMemorySize, YT_SMEM);

    yt_kernel<<<dim3(NN / 32, NS), 256, YT_SMEM>>>(x, W);
    gemm_kernel<<<dim3(NN / BM, NS), 256, SMEM_BYTES>>>(supports);
    reduce_kernel<<<(BB * NN * COUT) / (256 * 4), 256>>>(bias, out);
}

// round 9
// speedup vs baseline: 1.5288x; 1.4414x over previous
#include <cuda_runtime.h>
#include <cuda_fp16.h>
#include <cstdint>

// ---------------- problem constants ----------------
#define BB     8
#define NN     8192
#define CIN    32
#define COUT   32
#define NS     2
#define JCOLS  256        // B * C_OUT

// ---------------- GEMM tiling ----------------
#define BM     128
#define BN     256        // full J width
#define BK     32
#define NSTAGE 4
#define NKT    (NN / BK)  // 256

#define PADWF  36                       // f32 A stage row stride (words)
#define PADH   40                       // fp16 row stride (halves): 80B, LDSM conflict-free
#define AF32_STG_B  (BM * PADWF * 4)    // 18432 B per stage
#define B16_STG_B   (BN * PADH * 2)     // 20480 B per stage
#define AF32_OFF    0
#define B16_OFF     (NSTAGE * AF32_STG_B)                 // 73728
#define A16_OFF     (B16_OFF + NSTAGE * B16_STG_B)        // 155648
#define SMEM_BYTES  (A16_OFF + BM * PADH * 2)             // 165888

// ---------------- scratch ----------------
__device__ __align__(1024) __half g_yt16[(size_t)NS * JCOLS * NN];   // [s][j][m] fp16
__device__ __align__(1024) float  g_part[(size_t)NS * NN * JCOLS];   // [s][n][j]

// ---------------- PTX helpers (<= sm_80 base features only) ----------------
static __device__ __forceinline__ uint32_t smem_u32(const void* p) {
    uint32_t a;
    asm("{ .reg .u64 t; cvta.to.shared.u64 t, %1; cvt.u32.u64 %0, t; }" : "=r"(a) : "l"(p));
    return a;
}
#define CP16(dst, src) \
    asm volatile("cp.async.cg.shared.global [%0], [%1], 16;" :: "r"(dst), "l"(src) : "memory")
#define CPCOMMIT() asm volatile("cp.async.commit_group;" ::: "memory")
#define CPWAIT(n)  asm volatile("cp.async.wait_group %0;" :: "n"(n) : "memory")

#define LDSM_X4(r0, r1, r2, r3, addr) \
    asm volatile("ldmatrix.sync.aligned.m8n8.x4.shared.b16 {%0,%1,%2,%3}, [%4];" \
                 : "=r"(r0), "=r"(r1), "=r"(r2), "=r"(r3) : "r"(addr))

#define MMA_F16(d, a, b) \
    asm volatile("mma.sync.aligned.m16n8k16.row.col.f32.f16.f16.f32 " \
                 "{%0,%1,%2,%3}, {%4,%5,%6,%7}, {%8,%9}, {%0,%1,%2,%3};" \
                 : "+f"((d)[0]), "+f"((d)[1]), "+f"((d)[2]), "+f"((d)[3]) \
                 : "r"((a)[0]), "r"((a)[1]), "r"((a)[2]), "r"((a)[3]), \
                   "r"((b)[0]), "r"((b)[1]))

// ---- kernel 1: Yt[s][j][m] = sum_c x[b][m][c]*W[s][o][c]  (fp16-RN output) ----
#define YT_XS_W   (BB * 32 * CIN)          // 8192 floats
#define YT_WS_W   (COUT * 33)              // 1056 floats
#define YT_OUT_H  (JCOLS * 34)             // 8704 halves
#define YT_SMEM   ((YT_XS_W + YT_WS_W) * 4 + YT_OUT_H * 2)   // 54400 B

__global__ void __launch_bounds__(256) yt_kernel(const float* __restrict__ x,
                                                 const float* __restrict__ W) {
    extern __shared__ float sm[];
    float* xs = sm;                          // [b][m][c]
    float* ws = sm + YT_XS_W;                // [o][33]
    __half* outs = (__half*)(ws + YT_WS_W);  // [j][34]
    int s  = blockIdx.y;
    int m0 = blockIdx.x * 32;
    int t  = threadIdx.x;

    for (int i = t; i < COUT * CIN; i += 256)
        ws[(i >> 5) * 33 + (i & 31)] = W[s * COUT * CIN + i];
    for (int i = t; i < YT_XS_W; i += 256) {
        int b = i >> 10;
        xs[i] = x[(size_t)b * NN * CIN + (size_t)m0 * CIN + (i & 1023)];
    }
    __syncthreads();

    int b = t >> 5, o = t & 31;
    float wr[32];
#pragma unroll
    for (int c = 0; c < 32; ++c) wr[c] = ws[o * 33 + c];

    const float4* xr = (const float4*)(xs + b * 1024);
    __half* orow = outs + t * 34;
    for (int m = 0; m < 32; ++m) {
        float acc = 0.f;
#pragma unroll
        for (int q = 0; q < 8; ++q) {
            float4 v = xr[m * 8 + q];
            acc = fmaf(v.x, wr[q * 4 + 0], acc);
            acc = fmaf(v.y, wr[q * 4 + 1], acc);
            acc = fmaf(v.z, wr[q * 4 + 2], acc);
            acc = fmaf(v.w, wr[q * 4 + 3], acc);
        }
        orow[m] = __float2half_rn(acc);
    }
    __syncthreads();

    // coalesced uint (2-half) stores
    uint32_t* dst32 = (uint32_t*)g_yt16;
    for (int i = t; i < JCOLS * 16; i += 256) {
        int j = i >> 4, mp = i & 15;
        uint32_t v = *(const uint32_t*)(outs + j * 34 + 2 * mp);
        dst32[((((size_t)s * JCOLS + j) * NN + m0) >> 1) + mp] = v;
    }
}

// ---- kernel 2: fp16 mma.sync GEMM; A(f32) converted in-kernel ----
__global__ void __launch_bounds__(256, 1) gemm_kernel(const float* __restrict__ supports) {
    extern __shared__ char smc[];
    int tid  = threadIdx.x;
    int lane = tid & 31, w = tid >> 5;
    int wm = w >> 2, wn = w & 3;              // 2 (M) x 4 (N) warp grid, 64x64 each
    int n0 = blockIdx.x * BM;
    int s  = blockIdx.y;

    const float*  Abase = supports + ((size_t)s * NN + n0) * NN;
    const __half* Bbase = g_yt16 + (size_t)s * JCOLS * NN;
    uint32_t smb = smem_u32(smc);

    // ldmatrix lane offsets
    uint32_t a_row  = (uint32_t)(lane & 15);            // A: rows 0-15, k-half by lane>>4
    uint32_t a_koff = (uint32_t)((lane >> 4) << 3);     // halves
    uint32_t b_row  = (uint32_t)((lane & 7) + ((lane >> 4) << 3));
    uint32_t b_koff = (uint32_t)(((lane >> 3) & 1) << 3);

    // prologue: fill stages 0..2
#pragma unroll
    for (int p = 0; p < NSTAGE - 1; ++p) {
#pragma unroll
        for (int i = 0; i < 8; ++i) {
            int idx = i * 256 + tid;
            if (idx < 1024) {                  // A f32: 8 x 16B per row
                int r = idx >> 3, c = idx & 7;
                CP16(smb + AF32_OFF + p * AF32_STG_B + (uint32_t)(r * PADWF + c * 4) * 4,
                     Abase + (size_t)r * NN + (size_t)p * BK + c * 4);
            } else {                           // B fp16: 4 x 16B per row
                int bi = idx - 1024;
                int r = bi >> 2, c = bi & 3;
                CP16(smb + B16_OFF + p * B16_STG_B + (uint32_t)(r * PADH * 2 + c * 16),
                     Bbase + (size_t)r * NN + (size_t)p * BK + c * 8);
            }
        }
        CPCOMMIT();
    }

    float acc[4][8][4];
#pragma unroll
    for (int mt = 0; mt < 4; ++mt)
#pragma unroll
        for (int nt = 0; nt < 8; ++nt)
#pragma unroll
            for (int r = 0; r < 4; ++r) acc[mt][nt][r] = 0.f;

    int cr = tid >> 1, ch = tid & 1;          // convert mapping: row, half-of-row
    for (int kt = 0; kt < NKT; ++kt) {
        CPWAIT(2);
        __syncthreads();                      // stage kt (A f32 + B fp16) ready

        // convert A f32 stage -> fp16 buffer (16 floats/thread, conflict-free)
        {
            const float4* af = (const float4*)(smc + AF32_OFF + (kt & 3) * AF32_STG_B);
            int fi = cr * 9 + ch * 4;         // PADWF/4 = 9 float4 per row
            float4 v0 = af[fi], v1 = af[fi + 1], v2 = af[fi + 2], v3 = af[fi + 3];
            __half2 h[8];
            h[0] = __floats2half2_rn(v0.x, v0.y); h[1] = __floats2half2_rn(v0.z, v0.w);
            h[2] = __floats2half2_rn(v1.x, v1.y); h[3] = __floats2half2_rn(v1.z, v1.w);
            h[4] = __floats2half2_rn(v2.x, v2.y); h[5] = __floats2half2_rn(v2.z, v2.w);
            h[6] = __floats2half2_rn(v3.x, v3.y); h[7] = __floats2half2_rn(v3.z, v3.w);
            uint4* dst = (uint4*)(smc + A16_OFF + (cr * PADH + ch * 16) * 2);
            dst[0] = *(uint4*)&h[0];
            dst[1] = *(uint4*)&h[4];
        }

        int kn = kt + NSTAGE - 1;
        if (kn < NKT) {                       // refill the slot consumed at kt-1
#pragma unroll
            for (int i = 0; i < 8; ++i) {
                int idx = i * 256 + tid;
                if (idx < 1024) {
                    int r = idx >> 3, c = idx & 7;
                    CP16(smb + AF32_OFF + (kn & 3) * AF32_STG_B + (uint32_t)(r * PADWF + c * 4) * 4,
                         Abase + (size_t)r * NN + (size_t)kn * BK + c * 4);
                } else {
                    int bi = idx - 1024;
                    int r = bi >> 2, c = bi & 3;
                    CP16(smb + B16_OFF + (kn & 3) * B16_STG_B + (uint32_t)(r * PADH * 2 + c * 16),
                         Bbase + (size_t)r * NN + (size_t)kn * BK + c * 8);
                }
            }
            CPCOMMIT();
        }
        __syncthreads();                      // A16 buffer visible to all warps

        uint32_t A16 = smb + A16_OFF;
        uint32_t B16 = smb + B16_OFF + (kt & 3) * B16_STG_B;
#pragma unroll
        for (int kc = 0; kc < 2; ++kc) {      // two k16 chunks per BK=32
            uint32_t af4[4][4], bf[8][2];
#pragma unroll
            for (int mt = 0; mt < 4; ++mt) {
                uint32_t ad = A16 + (((uint32_t)(wm * 64 + mt * 16) + a_row) * PADH
                                     + kc * 16 + a_koff) * 2;
                LDSM_X4(af4[mt][0], af4[mt][1], af4[mt][2], af4[mt][3], ad);
            }
#pragma unroll
            for (int np = 0; np < 4; ++np) {  // each LDSM.x4 -> two n8 frags
                uint32_t bd = B16 + (((uint32_t)(wn * 64 + np * 16) + b_row) * PADH
                                     + kc * 16 + b_koff) * 2;
                LDSM_X4(bf[2 * np][0], bf[2 * np][1], bf[2 * np + 1][0], bf[2 * np + 1][1], bd);
            }
#pragma unroll
            for (int mt = 0; mt < 4; ++mt)
#pragma unroll
                for (int nt = 0; nt < 8; ++nt)
                    MMA_F16(acc[mt][nt], af4[mt], bf[nt]);
        }
    }

    // epilogue (same fragment layout as tf32: c0,c1=(g,2t); c2,c3=(g+8,2t))
    int g = lane >> 2, t4 = lane & 3;
    float* dst = g_part + ((size_t)s * NN + n0) * JCOLS;
#pragma unroll
    for (int mt = 0; mt < 4; ++mt) {
#pragma unroll
        for (int nt = 0; nt < 8; ++nt) {
            int row = wm * 64 + mt * 16 + g;
            int col = wn * 64 + nt * 8 + 2 * t4;
            *(float2*)(dst + (size_t)row * JCOLS + col) =
                make_float2(acc[mt][nt][0], acc[mt][nt][1]);
            *(float2*)(dst + (size_t)(row + 8) * JCOLS + col) =
                make_float2(acc[mt][nt][2], acc[mt][nt][3]);
        }
    }
}

// ---- kernel 3: out = part0 + part1 + bias (float4) ----
__global__ void __launch_bounds__(256) reduce_kernel(const float* __restrict__ bias,
                                                     float* __restrict__ out) {
    int idx = blockIdx.x * 256 + threadIdx.x;
    int o4 = (idx & 7) << 2;
    int n  = (idx >> 3) & (NN - 1);
    int b  = idx >> 16;
    size_t p = (size_t)n * JCOLS + (b << 5) + o4;
    const float4 p0 = *(const float4*)(g_part + p);
    const float4 p1 = *(const float4*)(g_part + (size_t)NN * JCOLS + p);
    const float4 bs = *(const float4*)(bias + o4);
    float4 r;
    r.x = p0.x + p1.x + bs.x;
    r.y = p0.y + p1.y + bs.y;
    r.z = p0.z + p1.z + bs.z;
    r.w = p0.w + p1.w + bs.w;
    *(float4*)(out + 4 * (size_t)idx) = r;
}

// ---------------- host ----------------
extern "C" void kernel_launch(void* const* d_in, const int* in_sizes, int n_in,
                              void* d_out, int out_size) {
    const float* x        = (const float*)d_in[0];
    const float* supports = (const float*)d_in[1];
    const float* W        = (const float*)d_in[2];
    const float* bias     = (const float*)d_in[3];
    float* out            = (float*)d_out;
    (void)in_sizes; (void)n_in; (void)out_size;

    cudaFuncSetAttribute(gemm_kernel, cudaFuncAttributeMaxDynamicSharedMemorySize, SMEM_BYTES);
    cudaFuncSetAttribute(yt_kernel, cudaFuncAttributeMaxDynamicSharedMemorySize, YT_SMEM);

    yt_kernel<<<dim3(NN / 32, NS), 256, YT_SMEM>>>(x, W);
    gemm_kernel<<<dim3(NN / BM, NS), 256, SMEM_BYTES>>>(supports);
    reduce_kernel<<<(BB * NN * COUT) / (256 * 4), 256>>>(bias, out);
}